// round 6
// baseline (speedup 1.0000x reference)
#include <cuda_runtime.h>
#include <cstdint>

// vanillaMLP fused. Round 6: per-cell 64B corner-records (2x2x2 neighborhood
// pre-gathered); 4 lanes cooperate per point so each warp-wide LDG.128 touches
// only 8 lines (8 points) instead of 32 -> gather wavefronts /4. MLP split
// across the quad (16 neurons/lane), quad butterfly shuffles for reductions.
// All fp32 (round-5 fp16 normals failure reverted).
// Outputs: [sigma N | fea N*16 | normals N*3 | grad N*3]

#define T_SIZE  524288
#define T_MASK  (T_SIZE - 1)
#define PRIME_Y 2654435761u
#define PRIME_Z 805459861u
#define DENSITY_BIAS (-1.0f)
#define CLAMP_MAX 10.0f

#define D0 18
#define D1 24
#define D2 32
#define D3 44
#define OFF0 0
#define OFF1 5832
#define OFF2 19656
#define OFF3 52424
#define NDENSE 137608

__device__ float4 g_dense[NDENSE + 64];
__device__ __align__(128) float4 g_rec[(size_t)NDENSE * 4];

typedef unsigned long long u64;

__device__ __forceinline__ u64 pk(float a, float b) {
    u64 r; asm("mov.b64 %0, {%1,%2};" : "=l"(r) : "f"(a), "f"(b)); return r;
}
__device__ __forceinline__ u64 pk2(float a) { return pk(a, a); }
__device__ __forceinline__ float2 upk(u64 v) {
    float2 r; asm("mov.b64 {%0,%1}, %2;" : "=f"(r.x), "=f"(r.y) : "l"(v)); return r;
}
__device__ __forceinline__ u64 fma2(u64 a, u64 b, u64 c) {
    u64 d; asm("fma.rn.f32x2 %0, %1, %2, %3;" : "=l"(d) : "l"(a), "l"(b), "l"(c)); return d;
}
__device__ __forceinline__ u64 mul2(u64 a, u64 b) {
    u64 d; asm("mul.rn.f32x2 %0, %1, %2;" : "=l"(d) : "l"(a), "l"(b)); return d;
}
__device__ __forceinline__ u64 add2(u64 a, u64 b) {
    u64 d; asm("add.rn.f32x2 %0, %1, %2;" : "=l"(d) : "l"(a), "l"(b)); return d;
}
__device__ __forceinline__ u64 neg2(u64 a) { return a ^ 0x8000000080000000ULL; }
__device__ __forceinline__ u64 shfl64(u64 v, int lanemask) {
    return __shfl_xor_sync(0xffffffffu, v, lanemask);
}

__global__ void __launch_bounds__(256)
build_dense_kernel(const float* __restrict__ table)
{
    int i = blockIdx.x * 256 + threadIdx.x;
    if (i >= NDENSE) return;
    int l, local, D;
    if (i < OFF1)      { l = 0; local = i;        D = D0; }
    else if (i < OFF2) { l = 1; local = i - OFF1; D = D1; }
    else if (i < OFF3) { l = 2; local = i - OFF2; D = D2; }
    else               { l = 3; local = i - OFF3; D = D3; }
    int z = local % D;
    int t = local / D;
    int y = t % D;
    int x = t / D;
    unsigned hb = (unsigned)x ^ ((unsigned)y * PRIME_Y);
    unsigned h0 = hb ^ ((unsigned)z * PRIME_Z);
    unsigned h1 = hb ^ ((unsigned)(z + 1) * PRIME_Z);
    const float2* __restrict__ tbl = (const float2*)table + (size_t)l * T_SIZE;
    float2 a = __ldg(tbl + (h0 & T_MASK));
    float2 b = __ldg(tbl + (h1 & T_MASK));
    g_dense[i] = make_float4(a.x, a.y, b.x, b.y);
}

__global__ void __launch_bounds__(256)
build_rec_kernel()
{
    int i = blockIdx.x * 256 + threadIdx.x;
    if (i >= NDENSE) return;
    int l, local, D, off;
    if (i < OFF1)      { l = 0; local = i;        D = D0; off = OFF0; }
    else if (i < OFF2) { l = 1; local = i - OFF1; D = D1; off = OFF1; }
    else if (i < OFF3) { l = 2; local = i - OFF2; D = D2; off = OFF2; }
    else               { l = 3; local = i - OFF3; D = D3; off = OFF3; }
    int z = local % D;
    int t = local / D;
    int y = t % D;
    int x = t / D;
    // border cells (x or y == D-1) are never gathered; clamp reads in-bounds
    int xs = min(x, D - 2);
    int ys = min(y, D - 2);
    int b = off + (xs * D + ys) * D + z;
    float4 v00 = g_dense[b];
    float4 v01 = g_dense[b + D];
    float4 v10 = g_dense[b + D * D];
    float4 v11 = g_dense[b + D * D + D];
    size_t ro = (size_t)i * 4;
    g_rec[ro + 0] = v00;
    g_rec[ro + 1] = v01;
    g_rec[ro + 2] = v10;
    g_rec[ro + 3] = v11;
}

__global__ void __launch_bounds__(256, 2)
nerf_fused_kernel(const float* __restrict__ pts,
                  const float* __restrict__ W1,
                  const float* __restrict__ W2,
                  float* __restrict__ out,
                  int n)
{
    __shared__ float w1s[64 * 8];    // W1 rows (first 8 cols), 32B/row
    __shared__ float w2p[64 * 20];   // W2 transposed rows, padded to 80B/row

    const int tid = threadIdx.x;
    for (int i = tid; i < 64 * 8; i += 256) {
        int j = i >> 3, k = i & 7;
        w1s[i] = W1[j * 32 + k];
    }
    for (int i = tid; i < 64 * 16; i += 256) {
        int j = i >> 4, k = i & 15;
        w2p[j * 20 + k] = W2[k * 64 + j];
    }
    __syncthreads();

    const int q  = tid & 3;              // lane role within quad
    const int p0 = blockIdx.x * 64 + (tid >> 2);
    const bool act = (p0 < n);
    const int p = act ? p0 : (n - 1);

    float x = (__ldg(pts + (size_t)p * 3 + 0) + 1.0f) * 0.5f;
    float y = (__ldg(pts + (size_t)p * 3 + 1) + 1.0f) * 0.5f;
    float z = (__ldg(pts + (size_t)p * 3 + 2) + 1.0f) * 0.5f;

    const float RES[4]  = {16.0f, 22.0f, 30.0f, 42.0f};
    const int   DIMS[4] = {D0, D1, D2, D3};
    const int   OFFS[4] = {OFF0, OFF1, OFF2, OFF3};

    const int ox = q >> 1, oy = q & 1;

    u64 feat2[4], axp[4], ayp[4], azp[4];

    #pragma unroll
    for (int l = 0; l < 4; l++) {
        const float res = RES[l];
        const int   D   = DIMS[l];
        float fx = x * res, fy = y * res, fz = z * res;
        float x0 = floorf(fx), y0 = floorf(fy), z0 = floorf(fz);
        float frx = fx - x0, fry = fy - y0, frz = fz - z0;
        float mfx = 1.0f - frx, mfy = 1.0f - fry, mfz = 1.0f - frz;
        int b00 = (((int)x0 * D + (int)y0) * D + (int)z0);

        float4 v = __ldg(g_rec + ((size_t)(OFFS[l] + b00)) * 4 + q);
        u64 t0 = pk(v.x, v.y), t1 = pk(v.z, v.w);
        u64 s = fma2(t0, pk2(mfz), mul2(t1, pk2(frz)));   // z-interp
        u64 d = add2(t1, neg2(t0));                        // z-derivative

        float wx = ox ? frx : mfx;
        float wy = oy ? fry : mfy;
        float wxy = wx * wy;
        feat2[l] = mul2(pk2(wxy), s);                  // this lane's corner-pair
        axp[l]   = mul2(pk2(ox ? wy : -wy), s);
        ayp[l]   = mul2(pk2(oy ? wx : -wx), s);
        azp[l]   = mul2(pk2(wxy), d);
    }

    // quad-reduce features (all 4 lanes end with the full per-level feature)
    #pragma unroll
    for (int l = 0; l < 4; l++) {
        feat2[l] = add2(feat2[l], shfl64(feat2[l], 1));
        feat2[l] = add2(feat2[l], shfl64(feat2[l], 2));
    }

    // ---- MLP split across the quad: lane q handles neurons j = 4i+q ----
    u64 fea2[8], dacc2[4];
    #pragma unroll
    for (int i = 0; i < 8; i++) fea2[i] = 0;
    #pragma unroll
    for (int l = 0; l < 4; l++) dacc2[l] = 0;

    #pragma unroll 4
    for (int it = 0; it < 16; it++) {
        int j = it * 4 + q;
        const float4* w1r = (const float4*)(w1s + j * 8);
        float4 wa = w1r[0], wb = w1r[1];
        u64 a0 = pk(wa.x, wa.y), a1 = pk(wa.z, wa.w);
        u64 a2 = pk(wb.x, wb.y), a3 = pk(wb.z, wb.w);

        u64 s = fma2(feat2[0], a0,
                fma2(feat2[1], a1,
                fma2(feat2[2], a2,
                mul2(feat2[3], a3))));
        float2 sp = upk(s);
        float hj = sp.x + sp.y;
        float hp = fmaxf(hj, 0.0f);
        u64 hp2 = pk2(hp);

        const float4* w2r = (const float4*)(w2p + j * 20);
        float4 c0 = w2r[0], c1 = w2r[1], c2 = w2r[2], c3 = w2r[3];
        fea2[0] = fma2(hp2, pk(c0.x, c0.y), fea2[0]);
        fea2[1] = fma2(hp2, pk(c0.z, c0.w), fea2[1]);
        fea2[2] = fma2(hp2, pk(c1.x, c1.y), fea2[2]);
        fea2[3] = fma2(hp2, pk(c1.z, c1.w), fea2[3]);
        fea2[4] = fma2(hp2, pk(c2.x, c2.y), fea2[4]);
        fea2[5] = fma2(hp2, pk(c2.z, c2.w), fea2[5]);
        fea2[6] = fma2(hp2, pk(c3.x, c3.y), fea2[6]);
        fea2[7] = fma2(hp2, pk(c3.z, c3.w), fea2[7]);

        float cm = (hj > 0.0f) ? c0.x : 0.0f;    // W2[0][j] gated by relu
        u64 cm2 = pk2(cm);
        dacc2[0] = fma2(cm2, a0, dacc2[0]);
        dacc2[1] = fma2(cm2, a1, dacc2[1]);
        dacc2[2] = fma2(cm2, a2, dacc2[2]);
        dacc2[3] = fma2(cm2, a3, dacc2[3]);
    }

    // quad-reduce MLP partials (sums over j-subsets)
    #pragma unroll
    for (int i = 0; i < 8; i++) {
        fea2[i] = add2(fea2[i], shfl64(fea2[i], 1));
        fea2[i] = add2(fea2[i], shfl64(fea2[i], 2));
    }
    #pragma unroll
    for (int l = 0; l < 4; l++) {
        dacc2[l] = add2(dacc2[l], shfl64(dacc2[l], 1));
        dacc2[l] = add2(dacc2[l], shfl64(dacc2[l], 2));
    }

    float2 fea01 = upk(fea2[0]);
    float pre   = fea01.x + DENSITY_BIAS;
    float sigma = expf(pre);
    float g     = expf(fminf(pre, CLAMP_MAX));

    // fold this lane's gather partials against the full dacc, then quad-reduce
    float gxp = 0.0f, gyp = 0.0f, gzp = 0.0f;
    #pragma unroll
    for (int l = 0; l < 4; l++) {
        float2 px = upk(mul2(dacc2[l], axp[l]));
        float2 py = upk(mul2(dacc2[l], ayp[l]));
        float2 pz = upk(mul2(dacc2[l], azp[l]));
        gxp = fmaf(RES[l], px.x + px.y, gxp);
        gyp = fmaf(RES[l], py.x + py.y, gyp);
        gzp = fmaf(RES[l], pz.x + pz.y, gzp);
    }
    gxp += __shfl_xor_sync(0xffffffffu, gxp, 1);
    gxp += __shfl_xor_sync(0xffffffffu, gxp, 2);
    gyp += __shfl_xor_sync(0xffffffffu, gyp, 1);
    gyp += __shfl_xor_sync(0xffffffffu, gyp, 2);
    gzp += __shfl_xor_sync(0xffffffffu, gzp, 1);
    gzp += __shfl_xor_sync(0xffffffffu, gzp, 2);

    float gx = gxp * g, gy = gyp * g, gz = gzp * g;
    float nrm = sqrtf(fmaf(gx, gx, fmaf(gy, gy, gz * gz)));
    float inv = 1.0f / nrm;

    if (act) {
        // fea: lane q writes float4 q -> warp writes 512B fully contiguous
        float2 fa = upk(fea2[2 * q]);
        float2 fb = upk(fea2[2 * q + 1]);
        ((float4*)(out + (size_t)n))[(size_t)p * 4 + q] =
            make_float4(fa.x, fa.y, fb.x, fb.y);
        if (q == 0) out[p] = sigma;
        if (q < 3) {
            float gv = (q == 0) ? gx : ((q == 1) ? gy : gz);
            out[(size_t)n * 17 + (size_t)p * 3 + q] = gv * inv;
            out[(size_t)n * 20 + (size_t)p * 3 + q] = gv;
        }
    }
}

extern "C" void kernel_launch(void* const* d_in, const int* in_sizes, int n_in,
                              void* d_out, int out_size)
{
    const float* pts   = (const float*)d_in[0];
    const float* table = (const float*)d_in[1];
    const float* W1    = (const float*)d_in[2];
    const float* W2    = (const float*)d_in[3];
    float* out = (float*)d_out;
    int n = in_sizes[0] / 3;

    build_dense_kernel<<<(NDENSE + 255) / 256, 256>>>(table);
    build_rec_kernel<<<(NDENSE + 255) / 256, 256>>>();
    nerf_fused_kernel<<<(n / 64) + ((n % 64) ? 1 : 0), 256>>>(pts, W1, W2, out, n);
}

// round 7
// speedup vs baseline: 1.7777x; 1.7777x over previous
#include <cuda_runtime.h>
#include <cstdint>

// vanillaMLP fused. Round 7: round-4 structure (1 thread/point; best 182.5us)
// + quad-cooperative record loading. Per-cell 64B corner-records: quad lanes
// load 16B quarters of each sibling point's record (one line per record ->
// 8 lines per warp LDG instead of 32), exchange through a padded smem stage.
// MLP / backward / outputs identical to round 4.
// Outputs: [sigma N | fea N*16 | normals N*3 | grad N*3]

#define T_SIZE  524288
#define T_MASK  (T_SIZE - 1)
#define PRIME_Y 2654435761u
#define PRIME_Z 805459861u
#define DENSITY_BIAS (-1.0f)
#define CLAMP_MAX 10.0f

#define D0 18
#define D1 24
#define D2 32
#define D3 44
#define OFF0 0
#define OFF1 5832
#define OFF2 19656
#define OFF3 52424
#define NDENSE 137608

__device__ float4 g_dense[NDENSE + 64];
__device__ __align__(128) float4 g_rec[(size_t)NDENSE * 4];

typedef unsigned long long u64;

__device__ __forceinline__ u64 pk(float a, float b) {
    u64 r; asm("mov.b64 %0, {%1,%2};" : "=l"(r) : "f"(a), "f"(b)); return r;
}
__device__ __forceinline__ u64 pk2(float a) { return pk(a, a); }
__device__ __forceinline__ float2 upk(u64 v) {
    float2 r; asm("mov.b64 {%0,%1}, %2;" : "=f"(r.x), "=f"(r.y) : "l"(v)); return r;
}
__device__ __forceinline__ u64 fma2(u64 a, u64 b, u64 c) {
    u64 d; asm("fma.rn.f32x2 %0, %1, %2, %3;" : "=l"(d) : "l"(a), "l"(b), "l"(c)); return d;
}
__device__ __forceinline__ u64 mul2(u64 a, u64 b) {
    u64 d; asm("mul.rn.f32x2 %0, %1, %2;" : "=l"(d) : "l"(a), "l"(b)); return d;
}
__device__ __forceinline__ u64 add2(u64 a, u64 b) {
    u64 d; asm("add.rn.f32x2 %0, %1, %2;" : "=l"(d) : "l"(a), "l"(b)); return d;
}
__device__ __forceinline__ u64 neg2(u64 a) { return a ^ 0x8000000080000000ULL; }

__global__ void __launch_bounds__(256)
build_dense_kernel(const float* __restrict__ table)
{
    int i = blockIdx.x * 256 + threadIdx.x;
    if (i >= NDENSE) return;
    int l, local, D;
    if (i < OFF1)      { l = 0; local = i;        D = D0; }
    else if (i < OFF2) { l = 1; local = i - OFF1; D = D1; }
    else if (i < OFF3) { l = 2; local = i - OFF2; D = D2; }
    else               { l = 3; local = i - OFF3; D = D3; }
    int z = local % D;
    int t = local / D;
    int y = t % D;
    int x = t / D;
    unsigned hb = (unsigned)x ^ ((unsigned)y * PRIME_Y);
    unsigned h0 = hb ^ ((unsigned)z * PRIME_Z);
    unsigned h1 = hb ^ ((unsigned)(z + 1) * PRIME_Z);
    const float2* __restrict__ tbl = (const float2*)table + (size_t)l * T_SIZE;
    float2 a = __ldg(tbl + (h0 & T_MASK));
    float2 b = __ldg(tbl + (h1 & T_MASK));
    g_dense[i] = make_float4(a.x, a.y, b.x, b.y);
}

__global__ void __launch_bounds__(256)
build_rec_kernel()
{
    int i = blockIdx.x * 256 + threadIdx.x;
    if (i >= NDENSE) return;
    int l, local, D, off;
    if (i < OFF1)      { l = 0; local = i;        D = D0; off = OFF0; }
    else if (i < OFF2) { l = 1; local = i - OFF1; D = D1; off = OFF1; }
    else if (i < OFF3) { l = 2; local = i - OFF2; D = D2; off = OFF2; }
    else               { l = 3; local = i - OFF3; D = D3; off = OFF3; }
    int z = local % D;
    int t = local / D;
    int y = t % D;
    int x = t / D;
    int xs = min(x, D - 2);           // border cells never gathered; clamp
    int ys = min(y, D - 2);
    int b = off + (xs * D + ys) * D + z;
    size_t ro = (size_t)i * 4;
    g_rec[ro + 0] = g_dense[b];
    g_rec[ro + 1] = g_dense[b + D];
    g_rec[ro + 2] = g_dense[b + D * D];
    g_rec[ro + 3] = g_dense[b + D * D + D];
}

__global__ void __launch_bounds__(128, 6)
nerf_fused_kernel(const float* __restrict__ pts,
                  const float* __restrict__ W1,
                  const float* __restrict__ W2,
                  float* __restrict__ out,
                  int n)
{
    __shared__ float4 w1f4[64 * 2];     // W1 rows, first 8 cols
    __shared__ float4 w2f4[64 * 4];     // W2 transposed rows
    __shared__ float4 sbufA[128 * 5];   // padded stage (stride 5 f4 = conflict-free)
    __shared__ float4 sbufB[128 * 5];

    const int tid = threadIdx.x;
    {
        float* w1s = (float*)w1f4;
        for (int i = tid; i < 64 * 8; i += 128) {
            int j = i >> 3, k = i & 7;
            w1s[i] = W1[j * 32 + k];
        }
        float* w2s = (float*)w2f4;
        for (int i = tid; i < 64 * 16; i += 128) {
            int j = i >> 4, k = i & 15;
            w2s[i] = W2[k * 64 + j];
        }
    }

    // coalesced point load through sbufA
    float* sf = (float*)sbufA;
    {
        size_t base = (size_t)blockIdx.x * 384;
        size_t lim3 = (size_t)n * 3;
        for (int i = tid; i < 384; i += 128) {
            size_t gi = base + i;
            sf[i] = (gi < lim3) ? pts[gi] : 0.0f;
        }
    }
    __syncthreads();

    const int pid = blockIdx.x * 128 + tid;
    const bool active = (pid < n);

    float x = (sf[tid * 3 + 0] + 1.0f) * 0.5f;
    float y = (sf[tid * 3 + 1] + 1.0f) * 0.5f;
    float z = (sf[tid * 3 + 2] + 1.0f) * 0.5f;
    __syncthreads();   // sbufA reused as gather stage / output stage

    const float RES[4]  = {16.0f, 22.0f, 30.0f, 42.0f};
    const int   DIMS[4] = {D0, D1, D2, D3};
    const int   OFFS[4] = {OFF0, OFF1, OFF2, OFF3};

    const int lane  = tid & 31;
    const int qbase = lane & ~3;        // quad leader lane
    const int lq    = lane & 3;         // quarter this lane loads

    u64 feat2[4], accx[4], accy[4], accz[4];

    #pragma unroll
    for (int l = 0; l < 4; l++) {
        const float res = RES[l];
        const int   D   = DIMS[l];
        float fx = x * res, fy = y * res, fz = z * res;
        float x0 = floorf(fx), y0 = floorf(fy), z0 = floorf(fz);
        float frx = fx - x0, fry = fy - y0, frz = fz - z0;
        float mfx = 1.0f - frx, mfy = 1.0f - fry, mfz = 1.0f - frz;
        int rec = OFFS[l] + (((int)x0 * D + (int)y0) * D + (int)z0);

        float4* sb = (l & 1) ? sbufB : sbufA;
        // cooperative load: quarter lq of each sibling point's 64B record
        #pragma unroll
        for (int i = 0; i < 4; i++) {
            int r = __shfl_sync(0xffffffffu, rec, qbase + i);
            float4 v = __ldg(g_rec + (size_t)r * 4 + lq);
            sb[((tid & ~31) + qbase + i) * 5 + lq] = v;
        }
        __syncwarp();
        float4 v00 = sb[tid * 5 + 0];
        float4 v01 = sb[tid * 5 + 1];
        float4 v10 = sb[tid * 5 + 2];
        float4 v11 = sb[tid * 5 + 3];

        u64 fz0 = pk2(mfz), fz1 = pk2(frz);
        u64 f01 = 0, ax = 0, ay = 0, az = 0;
        {   // (0,0)
            u64 t0 = pk(v00.x, v00.y), t1 = pk(v00.z, v00.w);
            u64 s = fma2(t0, fz0, mul2(t1, fz1));
            u64 d = add2(t1, neg2(t0));
            float wxy = mfx * mfy;
            f01 = fma2(pk2(wxy), s, f01);
            ax  = fma2(pk2(-mfy), s, ax);
            ay  = fma2(pk2(-mfx), s, ay);
            az  = fma2(pk2(wxy), d, az);
        }
        {   // (0,1)
            u64 t0 = pk(v01.x, v01.y), t1 = pk(v01.z, v01.w);
            u64 s = fma2(t0, fz0, mul2(t1, fz1));
            u64 d = add2(t1, neg2(t0));
            float wxy = mfx * fry;
            f01 = fma2(pk2(wxy), s, f01);
            ax  = fma2(pk2(-fry), s, ax);
            ay  = fma2(pk2( mfx), s, ay);
            az  = fma2(pk2(wxy), d, az);
        }
        {   // (1,0)
            u64 t0 = pk(v10.x, v10.y), t1 = pk(v10.z, v10.w);
            u64 s = fma2(t0, fz0, mul2(t1, fz1));
            u64 d = add2(t1, neg2(t0));
            float wxy = frx * mfy;
            f01 = fma2(pk2(wxy), s, f01);
            ax  = fma2(pk2( mfy), s, ax);
            ay  = fma2(pk2(-frx), s, ay);
            az  = fma2(pk2(wxy), d, az);
        }
        {   // (1,1)
            u64 t0 = pk(v11.x, v11.y), t1 = pk(v11.z, v11.w);
            u64 s = fma2(t0, fz0, mul2(t1, fz1));
            u64 d = add2(t1, neg2(t0));
            float wxy = frx * fry;
            f01 = fma2(pk2(wxy), s, f01);
            ax  = fma2(pk2( fry), s, ax);
            ay  = fma2(pk2( frx), s, ay);
            az  = fma2(pk2(wxy), d, az);
        }
        feat2[l] = f01; accx[l] = ax; accy[l] = ay; accz[l] = az;
        __syncwarp();   // reads done before this buffer's next reuse
    }

    // ---- fused MLP forward + backward-prep (f32x2) — identical to round 4 ----
    u64 fea2[8];
    u64 dacc2[4];
    #pragma unroll
    for (int i = 0; i < 8; i++) fea2[i] = 0;
    #pragma unroll
    for (int l = 0; l < 4; l++) dacc2[l] = 0;

    #pragma unroll 4
    for (int j = 0; j < 64; j++) {
        float4 wa = w1f4[j * 2 + 0];
        float4 wb = w1f4[j * 2 + 1];
        u64 a0 = pk(wa.x, wa.y), a1 = pk(wa.z, wa.w);
        u64 a2 = pk(wb.x, wb.y), a3 = pk(wb.z, wb.w);

        u64 s = fma2(feat2[0], a0,
                fma2(feat2[1], a1,
                fma2(feat2[2], a2,
                mul2(feat2[3], a3))));
        float2 sp = upk(s);
        float hj = sp.x + sp.y;
        float hp = fmaxf(hj, 0.0f);
        u64 hp2 = pk2(hp);

        float4 c0 = w2f4[j * 4 + 0];
        float4 c1 = w2f4[j * 4 + 1];
        float4 c2 = w2f4[j * 4 + 2];
        float4 c3 = w2f4[j * 4 + 3];
        fea2[0] = fma2(hp2, pk(c0.x, c0.y), fea2[0]);
        fea2[1] = fma2(hp2, pk(c0.z, c0.w), fea2[1]);
        fea2[2] = fma2(hp2, pk(c1.x, c1.y), fea2[2]);
        fea2[3] = fma2(hp2, pk(c1.z, c1.w), fea2[3]);
        fea2[4] = fma2(hp2, pk(c2.x, c2.y), fea2[4]);
        fea2[5] = fma2(hp2, pk(c2.z, c2.w), fea2[5]);
        fea2[6] = fma2(hp2, pk(c3.x, c3.y), fea2[6]);
        fea2[7] = fma2(hp2, pk(c3.z, c3.w), fea2[7]);

        float cm = (hj > 0.0f) ? c0.x : 0.0f;
        u64 cm2 = pk2(cm);
        dacc2[0] = fma2(cm2, a0, dacc2[0]);
        dacc2[1] = fma2(cm2, a1, dacc2[1]);
        dacc2[2] = fma2(cm2, a2, dacc2[2]);
        dacc2[3] = fma2(cm2, a3, dacc2[3]);
    }

    float2 fea01 = upk(fea2[0]);
    float pre   = fea01.x + DENSITY_BIAS;
    float sigma = expf(pre);
    float g     = expf(fminf(pre, CLAMP_MAX));

    float gx = 0.0f, gy = 0.0f, gz = 0.0f;
    #pragma unroll
    for (int l = 0; l < 4; l++) {
        float2 px = upk(mul2(dacc2[l], accx[l]));
        float2 py = upk(mul2(dacc2[l], accy[l]));
        float2 pz = upk(mul2(dacc2[l], accz[l]));
        gx = fmaf(RES[l], px.x + px.y, gx);
        gy = fmaf(RES[l], py.x + py.y, gy);
        gz = fmaf(RES[l], pz.x + pz.y, gz);
    }
    gx *= g; gy *= g; gz *= g;

    float nrm = sqrtf(fmaf(gx, gx, fmaf(gy, gy, gz * gz)));
    float inv = 1.0f / nrm;

    // ---- coalesced outputs via sbufA staging (round-4 scheme) ----
    if (active) out[pid] = sigma;

    const int npts = min(128, n - blockIdx.x * 128);

    __syncthreads();
    {
        float2 f0 = upk(fea2[0]), f1 = upk(fea2[1]);
        float2 f2 = upk(fea2[2]), f3 = upk(fea2[3]);
        float2 f4 = upk(fea2[4]), f5 = upk(fea2[5]);
        float2 f6 = upk(fea2[6]), f7 = upk(fea2[7]);
        sbufA[tid * 4 + 0] = make_float4(f0.x, f0.y, f1.x, f1.y);
        sbufA[tid * 4 + 1] = make_float4(f2.x, f2.y, f3.x, f3.y);
        sbufA[tid * 4 + 2] = make_float4(f4.x, f4.y, f5.x, f5.y);
        sbufA[tid * 4 + 3] = make_float4(f6.x, f6.y, f7.x, f7.y);
    }
    __syncthreads();
    {
        float4* dst = (float4*)(out + (size_t)n) + (size_t)blockIdx.x * 512;
        int lim = npts * 4;
        for (int i = tid; i < lim; i += 128) dst[i] = sbufA[i];
    }
    __syncthreads();

    sf[tid * 6 + 0] = gx * inv;
    sf[tid * 6 + 1] = gy * inv;
    sf[tid * 6 + 2] = gz * inv;
    sf[tid * 6 + 3] = gx;
    sf[tid * 6 + 4] = gy;
    sf[tid * 6 + 5] = gz;
    __syncthreads();
    {
        float* ndst = out + (size_t)n * 17 + (size_t)blockIdx.x * 384;
        float* gdst = out + (size_t)n * 20 + (size_t)blockIdx.x * 384;
        int lim = npts * 3;
        for (int i = tid; i < lim; i += 128) {
            int p = i / 3, c = i - p * 3;
            ndst[i] = sf[p * 6 + c];
        }
        for (int i = tid; i < lim; i += 128) {
            int p = i / 3, c = i - p * 3;
            gdst[i] = sf[p * 6 + 3 + c];
        }
    }
}

extern "C" void kernel_launch(void* const* d_in, const int* in_sizes, int n_in,
                              void* d_out, int out_size)
{
    const float* pts   = (const float*)d_in[0];
    const float* table = (const float*)d_in[1];
    const float* W1    = (const float*)d_in[2];
    const float* W2    = (const float*)d_in[3];
    float* out = (float*)d_out;
    int n = in_sizes[0] / 3;

    build_dense_kernel<<<(NDENSE + 255) / 256, 256>>>(table);
    build_rec_kernel<<<(NDENSE + 255) / 256, 256>>>();
    nerf_fused_kernel<<<(n + 127) / 128, 128>>>(pts, W1, W2, out, n);
}

// round 9
// speedup vs baseline: 2.3187x; 1.3043x over previous
#include <cuda_runtime.h>
#include <cstdint>

// vanillaMLP fused. Round 9: round-7 kernel (168.4us) with MLP weights moved
// from shared memory to __constant__ memory. Weight reads are warp-uniform ->
// LDC/ULDC on the constant port, removing ~384 broadcast LDS wavefronts/warp
// (the largest single L1tex consumer). Encode/backward/outputs unchanged.
// Outputs: [sigma N | fea N*16 | normals N*3 | grad N*3]

#define T_SIZE  524288
#define T_MASK  (T_SIZE - 1)
#define PRIME_Y 2654435761u
#define PRIME_Z 805459861u
#define DENSITY_BIAS (-1.0f)
#define CLAMP_MAX 10.0f

#define D0 18
#define D1 24
#define D2 32
#define D3 44
#define OFF0 0
#define OFF1 5832
#define OFF2 19656
#define OFF3 52424
#define NDENSE 137608

__device__ float4 g_dense[NDENSE + 64];
__device__ __align__(128) float4 g_rec[(size_t)NDENSE * 4];

// weight staging (device) and destination (constant)
__device__   float4 gW1r4[64 * 2];    // W1 rows, first 8 cols: [j][k/4]
__device__   float4 gW2t4[64 * 4];    // W2 transposed: [j][i/4] = W2[i][j]
__constant__ float4 cW1r4[64 * 2];
__constant__ float4 cW2t4[64 * 4];

typedef unsigned long long u64;

__device__ __forceinline__ u64 pk(float a, float b) {
    u64 r; asm("mov.b64 %0, {%1,%2};" : "=l"(r) : "f"(a), "f"(b)); return r;
}
__device__ __forceinline__ u64 pk2(float a) { return pk(a, a); }
__device__ __forceinline__ float2 upk(u64 v) {
    float2 r; asm("mov.b64 {%0,%1}, %2;" : "=f"(r.x), "=f"(r.y) : "l"(v)); return r;
}
__device__ __forceinline__ u64 fma2(u64 a, u64 b, u64 c) {
    u64 d; asm("fma.rn.f32x2 %0, %1, %2, %3;" : "=l"(d) : "l"(a), "l"(b), "l"(c)); return d;
}
__device__ __forceinline__ u64 mul2(u64 a, u64 b) {
    u64 d; asm("mul.rn.f32x2 %0, %1, %2;" : "=l"(d) : "l"(a), "l"(b)); return d;
}
__device__ __forceinline__ u64 add2(u64 a, u64 b) {
    u64 d; asm("add.rn.f32x2 %0, %1, %2;" : "=l"(d) : "l"(a), "l"(b)); return d;
}
__device__ __forceinline__ u64 neg2(u64 a) { return a ^ 0x8000000080000000ULL; }

__global__ void __launch_bounds__(256)
build_dense_kernel(const float* __restrict__ table)
{
    int i = blockIdx.x * 256 + threadIdx.x;
    if (i >= NDENSE) return;
    int l, local, D;
    if (i < OFF1)      { l = 0; local = i;        D = D0; }
    else if (i < OFF2) { l = 1; local = i - OFF1; D = D1; }
    else if (i < OFF3) { l = 2; local = i - OFF2; D = D2; }
    else               { l = 3; local = i - OFF3; D = D3; }
    int z = local % D;
    int t = local / D;
    int y = t % D;
    int x = t / D;
    unsigned hb = (unsigned)x ^ ((unsigned)y * PRIME_Y);
    unsigned h0 = hb ^ ((unsigned)z * PRIME_Z);
    unsigned h1 = hb ^ ((unsigned)(z + 1) * PRIME_Z);
    const float2* __restrict__ tbl = (const float2*)table + (size_t)l * T_SIZE;
    float2 a = __ldg(tbl + (h0 & T_MASK));
    float2 b = __ldg(tbl + (h1 & T_MASK));
    g_dense[i] = make_float4(a.x, a.y, b.x, b.y);
}

__global__ void __launch_bounds__(256)
build_rec_kernel()
{
    int i = blockIdx.x * 256 + threadIdx.x;
    if (i >= NDENSE) return;
    int l, local, D, off;
    if (i < OFF1)      { l = 0; local = i;        D = D0; off = OFF0; }
    else if (i < OFF2) { l = 1; local = i - OFF1; D = D1; off = OFF1; }
    else if (i < OFF3) { l = 2; local = i - OFF2; D = D2; off = OFF2; }
    else               { l = 3; local = i - OFF3; D = D3; off = OFF3; }
    int z = local % D;
    int t = local / D;
    int y = t % D;
    int x = t / D;
    int xs = min(x, D - 2);
    int ys = min(y, D - 2);
    int b = off + (xs * D + ys) * D + z;
    size_t ro = (size_t)i * 4;
    g_rec[ro + 0] = g_dense[b];
    g_rec[ro + 1] = g_dense[b + D];
    g_rec[ro + 2] = g_dense[b + D * D];
    g_rec[ro + 3] = g_dense[b + D * D + D];
}

__global__ void __launch_bounds__(256)
prep_weights_kernel(const float* __restrict__ W1, const float* __restrict__ W2)
{
    int i = threadIdx.x;
    if (i < 128) {            // W1 rows: gW1r4[j*2+h] = W1[j*32 + 4h .. 4h+3]
        int j = i >> 1, h = i & 1;
        const float* s = W1 + j * 32 + h * 4;
        gW1r4[i] = make_float4(s[0], s[1], s[2], s[3]);
    }
    if (i < 256) {            // W2 transposed: gW2t4[j*4+h].q = W2[(4h+q)*64 + j]
        int j = i >> 2, h = i & 3;
        gW2t4[i] = make_float4(W2[(4 * h + 0) * 64 + j], W2[(4 * h + 1) * 64 + j],
                               W2[(4 * h + 2) * 64 + j], W2[(4 * h + 3) * 64 + j]);
    }
}

__global__ void __launch_bounds__(128, 6)
nerf_fused_kernel(const float* __restrict__ pts,
                  float* __restrict__ out,
                  int n)
{
    __shared__ float4 sbufA[128 * 5];   // padded stage (stride 5 f4 = conflict-free)
    __shared__ float4 sbufB[128 * 5];

    const int tid = threadIdx.x;

    // coalesced point load through sbufA
    float* sf = (float*)sbufA;
    {
        size_t base = (size_t)blockIdx.x * 384;
        size_t lim3 = (size_t)n * 3;
        for (int i = tid; i < 384; i += 128) {
            size_t gi = base + i;
            sf[i] = (gi < lim3) ? pts[gi] : 0.0f;
        }
    }
    __syncthreads();

    const int pid = blockIdx.x * 128 + tid;
    const bool active = (pid < n);

    float x = (sf[tid * 3 + 0] + 1.0f) * 0.5f;
    float y = (sf[tid * 3 + 1] + 1.0f) * 0.5f;
    float z = (sf[tid * 3 + 2] + 1.0f) * 0.5f;
    __syncthreads();   // sbufA reused as gather stage / output stage

    const float RES[4]  = {16.0f, 22.0f, 30.0f, 42.0f};
    const int   DIMS[4] = {D0, D1, D2, D3};
    const int   OFFS[4] = {OFF0, OFF1, OFF2, OFF3};

    const int lane  = tid & 31;
    const int qbase = lane & ~3;        // quad leader lane
    const int lq    = lane & 3;         // quarter this lane loads

    u64 feat2[4], accx[4], accy[4], accz[4];

    #pragma unroll
    for (int l = 0; l < 4; l++) {
        const float res = RES[l];
        const int   D   = DIMS[l];
        float fx = x * res, fy = y * res, fz = z * res;
        float x0 = floorf(fx), y0 = floorf(fy), z0 = floorf(fz);
        float frx = fx - x0, fry = fy - y0, frz = fz - z0;
        float mfx = 1.0f - frx, mfy = 1.0f - fry, mfz = 1.0f - frz;
        int rec = OFFS[l] + (((int)x0 * D + (int)y0) * D + (int)z0);

        float4* sb = (l & 1) ? sbufB : sbufA;
        // cooperative load: quarter lq of each sibling point's 64B record
        #pragma unroll
        for (int i = 0; i < 4; i++) {
            int r = __shfl_sync(0xffffffffu, rec, qbase + i);
            float4 v = __ldg(g_rec + (size_t)r * 4 + lq);
            sb[((tid & ~31) + qbase + i) * 5 + lq] = v;
        }
        __syncwarp();
        float4 v00 = sb[tid * 5 + 0];
        float4 v01 = sb[tid * 5 + 1];
        float4 v10 = sb[tid * 5 + 2];
        float4 v11 = sb[tid * 5 + 3];

        u64 fz0 = pk2(mfz), fz1 = pk2(frz);
        u64 f01 = 0, ax = 0, ay = 0, az = 0;
        {   // (0,0)
            u64 t0 = pk(v00.x, v00.y), t1 = pk(v00.z, v00.w);
            u64 s = fma2(t0, fz0, mul2(t1, fz1));
            u64 d = add2(t1, neg2(t0));
            float wxy = mfx * mfy;
            f01 = fma2(pk2(wxy), s, f01);
            ax  = fma2(pk2(-mfy), s, ax);
            ay  = fma2(pk2(-mfx), s, ay);
            az  = fma2(pk2(wxy), d, az);
        }
        {   // (0,1)
            u64 t0 = pk(v01.x, v01.y), t1 = pk(v01.z, v01.w);
            u64 s = fma2(t0, fz0, mul2(t1, fz1));
            u64 d = add2(t1, neg2(t0));
            float wxy = mfx * fry;
            f01 = fma2(pk2(wxy), s, f01);
            ax  = fma2(pk2(-fry), s, ax);
            ay  = fma2(pk2( mfx), s, ay);
            az  = fma2(pk2(wxy), d, az);
        }
        {   // (1,0)
            u64 t0 = pk(v10.x, v10.y), t1 = pk(v10.z, v10.w);
            u64 s = fma2(t0, fz0, mul2(t1, fz1));
            u64 d = add2(t1, neg2(t0));
            float wxy = frx * mfy;
            f01 = fma2(pk2(wxy), s, f01);
            ax  = fma2(pk2( mfy), s, ax);
            ay  = fma2(pk2(-frx), s, ay);
            az  = fma2(pk2(wxy), d, az);
        }
        {   // (1,1)
            u64 t0 = pk(v11.x, v11.y), t1 = pk(v11.z, v11.w);
            u64 s = fma2(t0, fz0, mul2(t1, fz1));
            u64 d = add2(t1, neg2(t0));
            float wxy = frx * fry;
            f01 = fma2(pk2(wxy), s, f01);
            ax  = fma2(pk2( fry), s, ax);
            ay  = fma2(pk2( frx), s, ay);
            az  = fma2(pk2(wxy), d, az);
        }
        feat2[l] = f01; accx[l] = ax; accy[l] = ay; accz[l] = az;
        __syncwarp();   // reads done before this buffer's next reuse
    }

    // ---- fused MLP forward + backward-prep (f32x2), weights from constant ----
    u64 fea2[8];
    u64 dacc2[4];
    #pragma unroll
    for (int i = 0; i < 8; i++) fea2[i] = 0;
    #pragma unroll
    for (int l = 0; l < 4; l++) dacc2[l] = 0;

    #pragma unroll 4
    for (int j = 0; j < 64; j++) {
        float4 wa = cW1r4[j * 2 + 0];
        float4 wb = cW1r4[j * 2 + 1];
        u64 a0 = pk(wa.x, wa.y), a1 = pk(wa.z, wa.w);
        u64 a2 = pk(wb.x, wb.y), a3 = pk(wb.z, wb.w);

        u64 s = fma2(feat2[0], a0,
                fma2(feat2[1], a1,
                fma2(feat2[2], a2,
                mul2(feat2[3], a3))));
        float2 sp = upk(s);
        float hj = sp.x + sp.y;
        float hp = fmaxf(hj, 0.0f);
        u64 hp2 = pk2(hp);

        float4 c0 = cW2t4[j * 4 + 0];
        float4 c1 = cW2t4[j * 4 + 1];
        float4 c2 = cW2t4[j * 4 + 2];
        float4 c3 = cW2t4[j * 4 + 3];
        fea2[0] = fma2(hp2, pk(c0.x, c0.y), fea2[0]);
        fea2[1] = fma2(hp2, pk(c0.z, c0.w), fea2[1]);
        fea2[2] = fma2(hp2, pk(c1.x, c1.y), fea2[2]);
        fea2[3] = fma2(hp2, pk(c1.z, c1.w), fea2[3]);
        fea2[4] = fma2(hp2, pk(c2.x, c2.y), fea2[4]);
        fea2[5] = fma2(hp2, pk(c2.z, c2.w), fea2[5]);
        fea2[6] = fma2(hp2, pk(c3.x, c3.y), fea2[6]);
        fea2[7] = fma2(hp2, pk(c3.z, c3.w), fea2[7]);

        float cm = (hj > 0.0f) ? c0.x : 0.0f;   // W2[0][j] gated by relu mask
        u64 cm2 = pk2(cm);
        dacc2[0] = fma2(cm2, a0, dacc2[0]);
        dacc2[1] = fma2(cm2, a1, dacc2[1]);
        dacc2[2] = fma2(cm2, a2, dacc2[2]);
        dacc2[3] = fma2(cm2, a3, dacc2[3]);
    }

    float2 fea01 = upk(fea2[0]);
    float pre   = fea01.x + DENSITY_BIAS;
    float sigma = expf(pre);
    float g     = expf(fminf(pre, CLAMP_MAX));

    float gx = 0.0f, gy = 0.0f, gz = 0.0f;
    #pragma unroll
    for (int l = 0; l < 4; l++) {
        float2 px = upk(mul2(dacc2[l], accx[l]));
        float2 py = upk(mul2(dacc2[l], accy[l]));
        float2 pz = upk(mul2(dacc2[l], accz[l]));
        gx = fmaf(RES[l], px.x + px.y, gx);
        gy = fmaf(RES[l], py.x + py.y, gy);
        gz = fmaf(RES[l], pz.x + pz.y, gz);
    }
    gx *= g; gy *= g; gz *= g;

    float nrm = sqrtf(fmaf(gx, gx, fmaf(gy, gy, gz * gz)));
    float inv = 1.0f / nrm;

    // ---- coalesced outputs via sbufA staging ----
    if (active) out[pid] = sigma;

    const int npts = min(128, n - blockIdx.x * 128);

    __syncthreads();
    {
        float2 f0 = upk(fea2[0]), f1 = upk(fea2[1]);
        float2 f2 = upk(fea2[2]), f3 = upk(fea2[3]);
        float2 f4 = upk(fea2[4]), f5 = upk(fea2[5]);
        float2 f6 = upk(fea2[6]), f7 = upk(fea2[7]);
        sbufA[tid * 4 + 0] = make_float4(f0.x, f0.y, f1.x, f1.y);
        sbufA[tid * 4 + 1] = make_float4(f2.x, f2.y, f3.x, f3.y);
        sbufA[tid * 4 + 2] = make_float4(f4.x, f4.y, f5.x, f5.y);
        sbufA[tid * 4 + 3] = make_float4(f6.x, f6.y, f7.x, f7.y);
    }
    __syncthreads();
    {
        float4* dst = (float4*)(out + (size_t)n) + (size_t)blockIdx.x * 512;
        int lim = npts * 4;
        for (int i = tid; i < lim; i += 128) dst[i] = sbufA[i];
    }
    __syncthreads();

    sf[tid * 6 + 0] = gx * inv;
    sf[tid * 6 + 1] = gy * inv;
    sf[tid * 6 + 2] = gz * inv;
    sf[tid * 6 + 3] = gx;
    sf[tid * 6 + 4] = gy;
    sf[tid * 6 + 5] = gz;
    __syncthreads();
    {
        float* ndst = out + (size_t)n * 17 + (size_t)blockIdx.x * 384;
        float* gdst = out + (size_t)n * 20 + (size_t)blockIdx.x * 384;
        int lim = npts * 3;
        for (int i = tid; i < lim; i += 128) {
            int p = i / 3, c = i - p * 3;
            ndst[i] = sf[p * 6 + c];
        }
        for (int i = tid; i < lim; i += 128) {
            int p = i / 3, c = i - p * 3;
            gdst[i] = sf[p * 6 + 3 + c];
        }
    }
}

extern "C" void kernel_launch(void* const* d_in, const int* in_sizes, int n_in,
                              void* d_out, int out_size)
{
    const float* pts   = (const float*)d_in[0];
    const float* table = (const float*)d_in[1];
    const float* W1    = (const float*)d_in[2];
    const float* W2    = (const float*)d_in[3];
    float* out = (float*)d_out;
    int n = in_sizes[0] / 3;

    build_dense_kernel<<<(NDENSE + 255) / 256, 256>>>(table);
    build_rec_kernel<<<(NDENSE + 255) / 256, 256>>>();
    prep_weights_kernel<<<1, 256>>>(W1, W2);

    // stage -> constant (async D2D memcpy nodes; graph-capturable)
    void *c1 = nullptr, *c2 = nullptr, *g1 = nullptr, *g2 = nullptr;
    cudaGetSymbolAddress(&c1, cW1r4);
    cudaGetSymbolAddress(&c2, cW2t4);
    cudaGetSymbolAddress(&g1, gW1r4);
    cudaGetSymbolAddress(&g2, gW2t4);
    cudaMemcpyAsync(c1, g1, 64 * 2 * sizeof(float4), cudaMemcpyDeviceToDevice, 0);
    cudaMemcpyAsync(c2, g2, 64 * 4 * sizeof(float4), cudaMemcpyDeviceToDevice, 0);

    nerf_fused_kernel<<<(n + 127) / 128, 128>>>(pts, out, n);
}

// round 10
// speedup vs baseline: 2.4327x; 1.0491x over previous
#include <cuda_runtime.h>
#include <cstdint>

// vanillaMLP fused. Round 10: round-9 kernel (129.1us) with
//  - fused setup: g_rec built directly from hash table (one kernel), weight
//    prep folded into block 0 -> fewer launches / no g_dense intermediate
//  - single expf (g == sigma when pre < 10, else const e^10)
//  - packed f32x2 gradient fold (res pre-folded into dacc)
//  - MLP loop unroll 8
// Outputs: [sigma N | fea N*16 | normals N*3 | grad N*3]

#define T_SIZE  524288
#define T_MASK  (T_SIZE - 1)
#define PRIME_Y 2654435761u
#define PRIME_Z 805459861u
#define DENSITY_BIAS (-1.0f)
#define CLAMP_MAX 10.0f
#define EXP10F 22026.465794806718f

#define D0 18
#define D1 24
#define D2 32
#define D3 44
#define OFF0 0
#define OFF1 5832
#define OFF2 19656
#define OFF3 52424
#define NDENSE 137608
#define NREC (NDENSE * 4)

__device__ __align__(128) float4 g_rec[NREC + 8];

// weight staging (device) and destination (constant)
__device__   float4 gW1r4[64 * 2];    // W1 rows, first 8 cols: [j][k/4]
__device__   float4 gW2t4[64 * 4];    // W2 transposed: [j][i/4] = W2[i][j]
__constant__ float4 cW1r4[64 * 2];
__constant__ float4 cW2t4[64 * 4];

typedef unsigned long long u64;

__device__ __forceinline__ u64 pk(float a, float b) {
    u64 r; asm("mov.b64 %0, {%1,%2};" : "=l"(r) : "f"(a), "f"(b)); return r;
}
__device__ __forceinline__ u64 pk2(float a) { return pk(a, a); }
__device__ __forceinline__ float2 upk(u64 v) {
    float2 r; asm("mov.b64 {%0,%1}, %2;" : "=f"(r.x), "=f"(r.y) : "l"(v)); return r;
}
__device__ __forceinline__ u64 fma2(u64 a, u64 b, u64 c) {
    u64 d; asm("fma.rn.f32x2 %0, %1, %2, %3;" : "=l"(d) : "l"(a), "l"(b), "l"(c)); return d;
}
__device__ __forceinline__ u64 mul2(u64 a, u64 b) {
    u64 d; asm("mul.rn.f32x2 %0, %1, %2;" : "=l"(d) : "l"(a), "l"(b)); return d;
}
__device__ __forceinline__ u64 add2(u64 a, u64 b) {
    u64 d; asm("add.rn.f32x2 %0, %1, %2;" : "=l"(d) : "l"(a), "l"(b)); return d;
}
__device__ __forceinline__ u64 neg2(u64 a) { return a ^ 0x8000000080000000ULL; }

// ---- fused setup: corner-records straight from the hash table + weights ----
__global__ void __launch_bounds__(256)
setup_kernel(const float* __restrict__ table,
             const float* __restrict__ W1,
             const float* __restrict__ W2)
{
    int idx = blockIdx.x * 256 + threadIdx.x;
    if (idx < NREC) {
        int cell = idx >> 2, q = idx & 3;
        int l, local, D;
        if (cell < OFF1)      { l = 0; local = cell;        D = D0; }
        else if (cell < OFF2) { l = 1; local = cell - OFF1; D = D1; }
        else if (cell < OFF3) { l = 2; local = cell - OFF2; D = D2; }
        else                  { l = 3; local = cell - OFF3; D = D3; }
        int z = local % D;
        int t = local / D;
        int y = t % D;
        int x = t / D;
        int ox = q >> 1, oy = q & 1;
        unsigned hb = (unsigned)(x + ox) ^ ((unsigned)(y + oy) * PRIME_Y);
        unsigned h0 = hb ^ ((unsigned)z * PRIME_Z);
        unsigned h1 = hb ^ ((unsigned)(z + 1) * PRIME_Z);
        const float2* __restrict__ tbl = (const float2*)table + (size_t)l * T_SIZE;
        float2 a = __ldg(tbl + (h0 & T_MASK));
        float2 b = __ldg(tbl + (h1 & T_MASK));
        g_rec[idx] = make_float4(a.x, a.y, b.x, b.y);
    }
    if (blockIdx.x == 0) {
        int i = threadIdx.x;
        if (i < 128) {
            int j = i >> 1, h = i & 1;
            const float* s = W1 + j * 32 + h * 4;
            gW1r4[i] = make_float4(s[0], s[1], s[2], s[3]);
        }
        int j = i >> 2, h = i & 3;
        gW2t4[i] = make_float4(W2[(4 * h + 0) * 64 + j], W2[(4 * h + 1) * 64 + j],
                               W2[(4 * h + 2) * 64 + j], W2[(4 * h + 3) * 64 + j]);
    }
}

__global__ void __launch_bounds__(128, 6)
nerf_fused_kernel(const float* __restrict__ pts,
                  float* __restrict__ out,
                  int n)
{
    __shared__ float4 sbufA[128 * 5];   // padded stage (stride 5 f4 = conflict-free)
    __shared__ float4 sbufB[128 * 5];

    const int tid = threadIdx.x;

    // coalesced point load through sbufA
    float* sf = (float*)sbufA;
    {
        size_t base = (size_t)blockIdx.x * 384;
        size_t lim3 = (size_t)n * 3;
        for (int i = tid; i < 384; i += 128) {
            size_t gi = base + i;
            sf[i] = (gi < lim3) ? pts[gi] : 0.0f;
        }
    }
    __syncthreads();

    const int pid = blockIdx.x * 128 + tid;
    const bool active = (pid < n);

    float x = (sf[tid * 3 + 0] + 1.0f) * 0.5f;
    float y = (sf[tid * 3 + 1] + 1.0f) * 0.5f;
    float z = (sf[tid * 3 + 2] + 1.0f) * 0.5f;
    __syncthreads();   // sbufA reused as gather stage / output stage

    const float RES[4]  = {16.0f, 22.0f, 30.0f, 42.0f};
    const int   DIMS[4] = {D0, D1, D2, D3};
    const int   OFFS[4] = {OFF0, OFF1, OFF2, OFF3};

    const int lane  = tid & 31;
    const int qbase = lane & ~3;
    const int lq    = lane & 3;

    u64 feat2[4], accx[4], accy[4], accz[4];

    #pragma unroll
    for (int l = 0; l < 4; l++) {
        const float res = RES[l];
        const int   D   = DIMS[l];
        float fx = x * res, fy = y * res, fz = z * res;
        float x0 = floorf(fx), y0 = floorf(fy), z0 = floorf(fz);
        float frx = fx - x0, fry = fy - y0, frz = fz - z0;
        float mfx = 1.0f - frx, mfy = 1.0f - fry, mfz = 1.0f - frz;
        int rec = OFFS[l] + (((int)x0 * D + (int)y0) * D + (int)z0);

        float4* sb = (l & 1) ? sbufB : sbufA;
        #pragma unroll
        for (int i = 0; i < 4; i++) {
            int r = __shfl_sync(0xffffffffu, rec, qbase + i);
            float4 v = __ldg(g_rec + (size_t)r * 4 + lq);
            sb[((tid & ~31) + qbase + i) * 5 + lq] = v;
        }
        __syncwarp();
        float4 v00 = sb[tid * 5 + 0];
        float4 v01 = sb[tid * 5 + 1];
        float4 v10 = sb[tid * 5 + 2];
        float4 v11 = sb[tid * 5 + 3];

        u64 fz0 = pk2(mfz), fz1 = pk2(frz);
        u64 f01 = 0, ax = 0, ay = 0, az = 0;
        {   // (0,0)
            u64 t0 = pk(v00.x, v00.y), t1 = pk(v00.z, v00.w);
            u64 s = fma2(t0, fz0, mul2(t1, fz1));
            u64 d = add2(t1, neg2(t0));
            float wxy = mfx * mfy;
            f01 = fma2(pk2(wxy), s, f01);
            ax  = fma2(pk2(-mfy), s, ax);
            ay  = fma2(pk2(-mfx), s, ay);
            az  = fma2(pk2(wxy), d, az);
        }
        {   // (0,1)
            u64 t0 = pk(v01.x, v01.y), t1 = pk(v01.z, v01.w);
            u64 s = fma2(t0, fz0, mul2(t1, fz1));
            u64 d = add2(t1, neg2(t0));
            float wxy = mfx * fry;
            f01 = fma2(pk2(wxy), s, f01);
            ax  = fma2(pk2(-fry), s, ax);
            ay  = fma2(pk2( mfx), s, ay);
            az  = fma2(pk2(wxy), d, az);
        }
        {   // (1,0)
            u64 t0 = pk(v10.x, v10.y), t1 = pk(v10.z, v10.w);
            u64 s = fma2(t0, fz0, mul2(t1, fz1));
            u64 d = add2(t1, neg2(t0));
            float wxy = frx * mfy;
            f01 = fma2(pk2(wxy), s, f01);
            ax  = fma2(pk2( mfy), s, ax);
            ay  = fma2(pk2(-frx), s, ay);
            az  = fma2(pk2(wxy), d, az);
        }
        {   // (1,1)
            u64 t0 = pk(v11.x, v11.y), t1 = pk(v11.z, v11.w);
            u64 s = fma2(t0, fz0, mul2(t1, fz1));
            u64 d = add2(t1, neg2(t0));
            float wxy = frx * fry;
            f01 = fma2(pk2(wxy), s, f01);
            ax  = fma2(pk2( fry), s, ax);
            ay  = fma2(pk2( frx), s, ay);
            az  = fma2(pk2(wxy), d, az);
        }
        feat2[l] = f01; accx[l] = ax; accy[l] = ay; accz[l] = az;
        __syncwarp();
    }

    // ---- fused MLP forward + backward-prep (f32x2), weights from constant ----
    u64 fea2[8];
    u64 dacc2[4];
    #pragma unroll
    for (int i = 0; i < 8; i++) fea2[i] = 0;
    #pragma unroll
    for (int l = 0; l < 4; l++) dacc2[l] = 0;

    #pragma unroll 8
    for (int j = 0; j < 64; j++) {
        float4 wa = cW1r4[j * 2 + 0];
        float4 wb = cW1r4[j * 2 + 1];
        u64 a0 = pk(wa.x, wa.y), a1 = pk(wa.z, wa.w);
        u64 a2 = pk(wb.x, wb.y), a3 = pk(wb.z, wb.w);

        u64 s = fma2(feat2[0], a0,
                fma2(feat2[1], a1,
                fma2(feat2[2], a2,
                mul2(feat2[3], a3))));
        float2 sp = upk(s);
        float hj = sp.x + sp.y;
        float hp = fmaxf(hj, 0.0f);
        u64 hp2 = pk2(hp);

        float4 c0 = cW2t4[j * 4 + 0];
        float4 c1 = cW2t4[j * 4 + 1];
        float4 c2 = cW2t4[j * 4 + 2];
        float4 c3 = cW2t4[j * 4 + 3];
        fea2[0] = fma2(hp2, pk(c0.x, c0.y), fea2[0]);
        fea2[1] = fma2(hp2, pk(c0.z, c0.w), fea2[1]);
        fea2[2] = fma2(hp2, pk(c1.x, c1.y), fea2[2]);
        fea2[3] = fma2(hp2, pk(c1.z, c1.w), fea2[3]);
        fea2[4] = fma2(hp2, pk(c2.x, c2.y), fea2[4]);
        fea2[5] = fma2(hp2, pk(c2.z, c2.w), fea2[5]);
        fea2[6] = fma2(hp2, pk(c3.x, c3.y), fea2[6]);
        fea2[7] = fma2(hp2, pk(c3.z, c3.w), fea2[7]);

        float cm = (hj > 0.0f) ? c0.x : 0.0f;   // W2[0][j] gated by relu mask
        u64 cm2 = pk2(cm);
        dacc2[0] = fma2(cm2, a0, dacc2[0]);
        dacc2[1] = fma2(cm2, a1, dacc2[1]);
        dacc2[2] = fma2(cm2, a2, dacc2[2]);
        dacc2[3] = fma2(cm2, a3, dacc2[3]);
    }

    float2 fea01 = upk(fea2[0]);
    float pre   = fea01.x + DENSITY_BIAS;
    float sigma = expf(pre);
    float g     = (pre < CLAMP_MAX) ? sigma : EXP10F;

    // ---- packed gradient fold: res pre-folded into dacc ----
    #pragma unroll
    for (int l = 0; l < 4; l++) dacc2[l] = mul2(dacc2[l], pk2(RES[l]));
    u64 gx2 = 0, gy2 = 0, gz2 = 0;
    #pragma unroll
    for (int l = 0; l < 4; l++) {
        gx2 = fma2(dacc2[l], accx[l], gx2);
        gy2 = fma2(dacc2[l], accy[l], gy2);
        gz2 = fma2(dacc2[l], accz[l], gz2);
    }
    float2 pxx = upk(gx2), pyy = upk(gy2), pzz = upk(gz2);
    float gx = (pxx.x + pxx.y) * g;
    float gy = (pyy.x + pyy.y) * g;
    float gz = (pzz.x + pzz.y) * g;

    float nrm = sqrtf(fmaf(gx, gx, fmaf(gy, gy, gz * gz)));
    float inv = 1.0f / nrm;

    // ---- coalesced outputs via sbufA staging ----
    if (active) out[pid] = sigma;

    const int npts = min(128, n - blockIdx.x * 128);

    __syncthreads();
    {
        float2 f0 = upk(fea2[0]), f1 = upk(fea2[1]);
        float2 f2 = upk(fea2[2]), f3 = upk(fea2[3]);
        float2 f4 = upk(fea2[4]), f5 = upk(fea2[5]);
        float2 f6 = upk(fea2[6]), f7 = upk(fea2[7]);
        sbufA[tid * 4 + 0] = make_float4(f0.x, f0.y, f1.x, f1.y);
        sbufA[tid * 4 + 1] = make_float4(f2.x, f2.y, f3.x, f3.y);
        sbufA[tid * 4 + 2] = make_float4(f4.x, f4.y, f5.x, f5.y);
        sbufA[tid * 4 + 3] = make_float4(f6.x, f6.y, f7.x, f7.y);
    }
    __syncthreads();
    {
        float4* dst = (float4*)(out + (size_t)n) + (size_t)blockIdx.x * 512;
        int lim = npts * 4;
        for (int i = tid; i < lim; i += 128) dst[i] = sbufA[i];
    }
    __syncthreads();

    sf[tid * 6 + 0] = gx * inv;
    sf[tid * 6 + 1] = gy * inv;
    sf[tid * 6 + 2] = gz * inv;
    sf[tid * 6 + 3] = gx;
    sf[tid * 6 + 4] = gy;
    sf[tid * 6 + 5] = gz;
    __syncthreads();
    {
        float* ndst = out + (size_t)n * 17 + (size_t)blockIdx.x * 384;
        float* gdst = out + (size_t)n * 20 + (size_t)blockIdx.x * 384;
        int lim = npts * 3;
        for (int i = tid; i < lim; i += 128) {
            int p = i / 3, c = i - p * 3;
            ndst[i] = sf[p * 6 + c];
        }
        for (int i = tid; i < lim; i += 128) {
            int p = i / 3, c = i - p * 3;
            gdst[i] = sf[p * 6 + 3 + c];
        }
    }
}

extern "C" void kernel_launch(void* const* d_in, const int* in_sizes, int n_in,
                              void* d_out, int out_size)
{
    const float* pts   = (const float*)d_in[0];
    const float* table = (const float*)d_in[1];
    const float* W1    = (const float*)d_in[2];
    const float* W2    = (const float*)d_in[3];
    float* out = (float*)d_out;
    int n = in_sizes[0] / 3;

    setup_kernel<<<(NREC + 255) / 256, 256>>>(table, W1, W2);

    void *c1 = nullptr, *c2 = nullptr, *g1 = nullptr, *g2 = nullptr;
    cudaGetSymbolAddress(&c1, cW1r4);
    cudaGetSymbolAddress(&c2, cW2t4);
    cudaGetSymbolAddress(&g1, gW1r4);
    cudaGetSymbolAddress(&g2, gW2t4);
    cudaMemcpyAsync(c1, g1, 64 * 2 * sizeof(float4), cudaMemcpyDeviceToDevice, 0);
    cudaMemcpyAsync(c2, g2, 64 * 4 * sizeof(float4), cudaMemcpyDeviceToDevice, 0);

    nerf_fused_kernel<<<(n + 127) / 128, 128>>>(pts, out, n);
}